// round 17
// baseline (speedup 1.0000x reference)
#include <cuda_runtime.h>
#include <math.h>

typedef unsigned long long ull;

// Memory plan (~20.2KB smem) — identical to R16:
//  F[2048]: right envs; env of bond j at slot (j-1)*256, j=1..8 (16x16, stride 16)
//  M[1088]: raw absorbed middle tensor (16,16,4): [l*68 + r*4 + d]; site0/9 flat 64
//  A[1088]: arena.
//    Phase A: T (stride-68 env temp) = A[0..1087]; tb = A[320..575]
//    Phase B: m = A[0..319] (stride 20), W = A[320..575] (stride 16),
//             G = A[576..895] (col-major stride 20), sv = A[896..959]
//    Zip:     botS register dump = A[0..639]
//  peps loads software-pipelined (ldg8/commit8).
//  Jacobi: systolic Brent-Luk — each quad holds its pair's two columns in
//  registers; rounds use shfl only (no smem, no syncwarp).

struct SM {
    float F[2048];
    float M[1088];
    float A[1088];
    float small[640];
    float Eb[16], Eb2[16];
    float cn[16];
    float invn[4];
    float logn;
    int   kidx[4];
    int   xr[100];
};

__device__ __forceinline__ float wsum(float v) {
    #pragma unroll
    for (int o = 16; o > 0; o >>= 1) v += __shfl_xor_sync(0xffffffffu, v, o);
    return v;
}
__device__ __forceinline__ float d4(float4 a, float4 b) {
    return a.x * b.x + a.y * b.y + a.z * b.z + a.w * b.w;
}

// Pipelined peps staging.
__device__ __forceinline__ void ldg8(const float* __restrict__ peps, int site, int xp,
                                     float v[8], int lane) {
    const float* base = peps + (size_t)site * 512;
    #pragma unroll
    for (int t = 0; t < 8; t++) v[t] = base[(lane + 32 * t) * 2 + xp];
}
__device__ __forceinline__ void commit8(SM* s, const float v[8], int lane) {
    float* tb = s->A + 320;
    #pragma unroll
    for (int t = 0; t < 8; t++) tb[lane + 32 * t] = v[t];
}

template<bool TOP>
__device__ __forceinline__ float tslice(SM* s, int v, int ph, int il, int ic) {
    int idx = TOP ? (((ph * 4 + v) * 4 + il) * 4 + ic)
                  : (((v * 4 + ph) * 4 + il) * 4 + ic);
    return s->A[320 + idx];
}

template<bool TOP>
__device__ void absorbM(SM* s, int j, int lane) {
    const float* sm = s->small + j * 64;
    int r = lane & 15, hw = lane >> 4;
    int b = r >> 2, ic = r & 3;
    float4 mr0 = *(const float4*)(sm + ((2 * hw) * 4 + b) * 4);
    float4 mr1 = *(const float4*)(sm + ((2 * hw + 1) * 4 + b) * 4);
    #pragma unroll
    for (int lt = 0; lt < 8; lt++) {
        int l = 8 * hw + lt;
        int il = lt & 3;
        float4 mr = (lt < 4) ? mr0 : mr1;
        float acc[4];
        #pragma unroll
        for (int ph = 0; ph < 4; ph++) {
            float a = mr.x * tslice<TOP>(s, 0, ph, il, ic)
                    + mr.y * tslice<TOP>(s, 1, ph, il, ic)
                    + mr.z * tslice<TOP>(s, 2, ph, il, ic)
                    + mr.w * tslice<TOP>(s, 3, ph, il, ic);
            acc[ph] = a;
        }
        *(float4*)(s->M + l * 68 + r * 4) = make_float4(acc[0], acc[1], acc[2], acc[3]);
    }
}

template<bool TOP>
__device__ void absorb0(SM* s, int lane) {
    const float* sm = s->small;
    #pragma unroll
    for (int t = 0; t < 2; t++) {
        int e = lane + 32 * t;
        int ph = e & 3, r = e >> 2;
        int b = r >> 2, ic = r & 3;
        const float* mr = sm + b * 4;
        float acc = 0.f;
        #pragma unroll
        for (int v = 0; v < 4; v++) acc += mr[v] * tslice<TOP>(s, v, ph, 0, ic);
        s->M[e] = acc;  // [r*4+ph]
    }
}

template<bool TOP>
__device__ void absorb9(SM* s, int lane) {
    const float* sm = s->small + 9 * 64;
    #pragma unroll
    for (int t = 0; t < 2; t++) {
        int e = lane + 32 * t;
        int ph = e & 3, l = e >> 2;
        int a = l >> 2, il = l & 3;
        const float* mr = sm + a * 4;
        float acc = 0.f;
        #pragma unroll
        for (int v = 0; v < 4; v++) acc += mr[v] * tslice<TOP>(s, v, ph, il, 0);
        s->M[e] = acc;  // [l*4+ph]
    }
}

// env(bond j-1) = sum_d M_j env(bond j) M_j^T.
__device__ void envM(SM* s, int j, int lane) {
    const float* Fj = s->F + (j - 1) * 256;
    float* T = s->A;
    #pragma unroll
    for (int g = 0; g < 2; g++) {
        int idx = lane + 32 * g;          // idx = 4*l + d
        int l = idx >> 2, d = idx & 3;
        float Mr[16];
        #pragma unroll
        for (int r2 = 0; r2 < 16; r2++) Mr[r2] = s->M[l * 68 + r2 * 4 + d];
        float4 acc0 = make_float4(0.f, 0.f, 0.f, 0.f);
        float4 acc1 = make_float4(0.f, 0.f, 0.f, 0.f);
        float4 acc2 = make_float4(0.f, 0.f, 0.f, 0.f);
        float4 acc3 = make_float4(0.f, 0.f, 0.f, 0.f);
        #pragma unroll
        for (int r2 = 0; r2 < 16; r2++) {
            const float4* Fr = (const float4*)(Fj + r2 * 16);
            float mv = Mr[r2];
            float4 f0 = Fr[0], f1 = Fr[1], f2 = Fr[2], f3 = Fr[3];
            acc0.x += mv * f0.x; acc0.y += mv * f0.y; acc0.z += mv * f0.z; acc0.w += mv * f0.w;
            acc1.x += mv * f1.x; acc1.y += mv * f1.y; acc1.z += mv * f1.z; acc1.w += mv * f1.w;
            acc2.x += mv * f2.x; acc2.y += mv * f2.y; acc2.z += mv * f2.z; acc2.w += mv * f2.w;
            acc3.x += mv * f3.x; acc3.y += mv * f3.y; acc3.z += mv * f3.z; acc3.w += mv * f3.w;
        }
        T[l * 68 + 0 * 4 + d]  = acc0.x; T[l * 68 + 1 * 4 + d]  = acc0.y;
        T[l * 68 + 2 * 4 + d]  = acc0.z; T[l * 68 + 3 * 4 + d]  = acc0.w;
        T[l * 68 + 4 * 4 + d]  = acc1.x; T[l * 68 + 5 * 4 + d]  = acc1.y;
        T[l * 68 + 6 * 4 + d]  = acc1.z; T[l * 68 + 7 * 4 + d]  = acc1.w;
        T[l * 68 + 8 * 4 + d]  = acc2.x; T[l * 68 + 9 * 4 + d]  = acc2.y;
        T[l * 68 + 10 * 4 + d] = acc2.z; T[l * 68 + 11 * 4 + d] = acc2.w;
        T[l * 68 + 12 * 4 + d] = acc3.x; T[l * 68 + 13 * 4 + d] = acc3.y;
        T[l * 68 + 14 * 4 + d] = acc3.z; T[l * 68 + 15 * 4 + d] = acc3.w;
    }
    __syncwarp();
    float* Fn = s->F + (j - 2) * 256;
    {
        int pr2 = lane >> 2, qd = lane & 3;
        int l1a = 2 * pr2;
        const float4* Ta = (const float4*)(T + l1a * 68);
        const float4* Tb = (const float4*)(T + (l1a + 1) * 68);
        const float4* M0 = (const float4*)(s->M + (4 * qd + 0) * 68);
        const float4* M1 = (const float4*)(s->M + (4 * qd + 1) * 68);
        const float4* M2 = (const float4*)(s->M + (4 * qd + 2) * 68);
        const float4* M3 = (const float4*)(s->M + (4 * qd + 3) * 68);
        float a0 = 0.f, a1 = 0.f, a2 = 0.f, a3 = 0.f;
        float b0 = 0.f, b1 = 0.f, b2 = 0.f, b3 = 0.f;
        #pragma unroll
        for (int q = 0; q < 16; q++) {
            float4 ta = Ta[q], tb = Tb[q];
            float4 m0 = M0[q]; a0 += d4(ta, m0); b0 += d4(tb, m0);
            float4 m1 = M1[q]; a1 += d4(ta, m1); b1 += d4(tb, m1);
            float4 m2 = M2[q]; a2 += d4(ta, m2); b2 += d4(tb, m2);
            float4 m3 = M3[q]; a3 += d4(ta, m3); b3 += d4(tb, m3);
        }
        *(float4*)(Fn + l1a * 16 + 4 * qd)       = make_float4(a0, a1, a2, a3);
        *(float4*)(Fn + (l1a + 1) * 16 + 4 * qd) = make_float4(b0, b1, b2, b3);
    }
    __syncwarp();
}

__device__ __forceinline__ int pairP(int k, int rnd) {
    return (k == 0) ? 0 : ((k - 1 + rnd) % 15) + 1;
}
__device__ __forceinline__ int pairQ(int k, int rnd) {
    return ((14 - k + rnd) % 15) + 1;
}

// Systolic (Brent-Luk) one-sided Jacobi. Quad qd holds columns P,Q in registers
// (lane ql owns rows ql*4..ql*4+3). Transition per round:
//   newP(k)=oldP(k+1) k=1..6; newP(7)=own oldQ; P(0) pinned;
//   newQ(k)=oldQ(k-1) k=1..7; newQ(0)=oldP(1).
// Exchange via shfl; no smem, no syncwarp inside the loop. Returns rounds done.
__device__ int jacobiSys(float* Gc, int lane) {
    int qd = lane >> 2, ql = lane & 3;
    float4 P = *(float4*)(Gc + qd * 20 + ql * 4);
    float4 Q = *(float4*)(Gc + (15 - qd) * 20 + ql * 4);
    int up = (lane + 4) & 31, dn = (lane - 4) & 31;
    int rnd = 0;
    for (int sw = 0; sw < 6; sw++) {
        int flag = 0;
        #pragma unroll
        for (int r15 = 0; r15 < 15; r15++) {
            float dpp = d4(P, P), dqq = d4(Q, Q), dpq = d4(P, Q);
            dpp += __shfl_xor_sync(0xffffffffu, dpp, 1);
            dpp += __shfl_xor_sync(0xffffffffu, dpp, 2);
            dqq += __shfl_xor_sync(0xffffffffu, dqq, 1);
            dqq += __shfl_xor_sync(0xffffffffu, dqq, 2);
            dpq += __shfl_xor_sync(0xffffffffu, dpq, 1);
            dpq += __shfl_xor_sync(0xffffffffu, dpq, 2);
            float den = dpp * dqq;
            float r2 = dpq * dpq;
            flag |= (r2 > 1e-9f * den) ? 1 : 0;
            bool rot = (r2 > 1e-30f * den) && (r2 > 0.f);
            float xd = rot ? (2.f * dpq) : 1.f;
            float ta = (dqq - dpp) / xd;
            float tt = ((ta >= 0.f) ? 1.f : -1.f) / (fabsf(ta) + sqrtf(1.f + ta * ta));
            float cc = rsqrtf(1.f + tt * tt);
            float ssn = tt * cc;
            float c = rot ? cc : 1.f;
            float sn = rot ? ssn : 0.f;
            float4 nP, nQ;
            nP.x = c * P.x - sn * Q.x; nQ.x = sn * P.x + c * Q.x;
            nP.y = c * P.y - sn * Q.y; nQ.y = sn * P.y + c * Q.y;
            nP.z = c * P.z - sn * Q.z; nQ.z = sn * P.z + c * Q.z;
            nP.w = c * P.w - sn * Q.w; nQ.w = sn * P.w + c * Q.w;
            // exchange
            float4 tA, tB;
            tA.x = __shfl_sync(0xffffffffu, nP.x, up);
            tA.y = __shfl_sync(0xffffffffu, nP.y, up);
            tA.z = __shfl_sync(0xffffffffu, nP.z, up);
            tA.w = __shfl_sync(0xffffffffu, nP.w, up);
            tB.x = __shfl_sync(0xffffffffu, nQ.x, dn);
            tB.y = __shfl_sync(0xffffffffu, nQ.y, dn);
            tB.z = __shfl_sync(0xffffffffu, nQ.z, dn);
            tB.w = __shfl_sync(0xffffffffu, nQ.w, dn);
            if (qd == 0)      { P = nP; Q = tA; }
            else if (qd == 7) { P = nQ; Q = tB; }
            else              { P = tA; Q = tB; }
        }
        rnd += 15;
        if (sw >= 1 && !__any_sync(0xffffffffu, flag)) break;
    }
    // write holdings back to smem G at their current column indices
    int pi = pairP(qd, rnd % 15), qi = pairQ(qd, rnd % 15);
    *(float4*)(Gc + pi * 20 + ql * 4) = P;
    *(float4*)(Gc + qi * 20 + ql * 4) = Q;
    return rnd;
}

template<bool TOP>
__device__ void initRow(SM* s, const float* __restrict__ peps, int i, int lane) {
    float v[8];
    ldg8(peps, i * 10 + 0, s->xr[i * 10 + 0], v, lane);
    for (int j = 0; j < 10; j++) {
        commit8(s, v, lane);
        __syncwarp();
        if (j < 9) ldg8(peps, i * 10 + j + 1, s->xr[i * 10 + j + 1], v, lane);
        if (j == 9) {
            if (lane < 16) {
                int ph = lane & 3, il = lane >> 2;
                s->small[9 * 64 + lane] = tslice<TOP>(s, 0, ph, il, 0);
            }
        } else {
            int n = (j == 0) ? 16 : 64;
            for (int e = lane; e < n; e += 32) {
                int ph = e & 3, ic = (e >> 2) & 3, il = e >> 4;
                s->small[j * 64 + e] = tslice<TOP>(s, 0, ph, il, ic);
            }
        }
        __syncwarp();
    }
}

template<bool TOP>
__device__ void compress(SM* s, const float* __restrict__ peps, int i, int lane, int) {
    float* m  = s->A;          // stride 20
    float* W  = s->A + 320;    // stride 16
    float* G  = s->A + 576;    // col-major stride 20
    float* sv = s->A + 896;
    int rfix = lane & 15;
    int hw = lane >> 4;
    int b10 = i * 10;
    float v[8];
    // ---- Phase A: right environments ----
    ldg8(peps, b10 + 9, s->xr[b10 + 9], v, lane);
    commit8(s, v, lane); __syncwarp();
    ldg8(peps, b10 + 8, s->xr[b10 + 8], v, lane);
    absorb9<TOP>(s, lane); __syncwarp();
    #pragma unroll
    for (int t = 0; t < 8; t++) {
        int e = lane + 32 * t; int l = e >> 4, l2 = e & 15;
        float acc = 0.f;
        #pragma unroll
        for (int d = 0; d < 4; d++) acc += s->M[l * 4 + d] * s->M[l2 * 4 + d];
        s->F[7 * 256 + e] = acc;   // env of bond 8 at slot 7
    }
    __syncwarp();
    for (int j = 8; j >= 2; j--) {
        commit8(s, v, lane); __syncwarp();
        int nj = (j > 2) ? (j - 1) : 0;
        ldg8(peps, b10 + nj, s->xr[b10 + nj], v, lane);
        absorbM<TOP>(s, j, lane); __syncwarp();
        envM(s, j, lane);
    }
    // ---- Phase B: left sweep ----
    commit8(s, v, lane); __syncwarp();
    ldg8(peps, b10 + 1, s->xr[b10 + 1], v, lane);
    absorb0<TOP>(s, lane); __syncwarp();
    if (lane < 16) {
        int b = lane >> 2, d = lane & 3;
        s->small[b * 4 + d] = (b == d) ? 1.f : 0.f;   // site 0: keep-all, U = I gauge
    }
    #pragma unroll
    for (int t = 0; t < 2; t++) {
        int e = lane + 32 * t; int r = e & 15, dd = e >> 4;
        sv[dd * 16 + r] = s->M[r * 4 + dd];
    }
    __syncwarp();
    for (int j = 1; j <= 8; j++) {
        commit8(s, v, lane); __syncwarp();
        int nj = (j < 8) ? (j + 1) : 9;
        ldg8(peps, b10 + nj, s->xr[b10 + nj], v, lane);
        absorbM<TOP>(s, j, lane); __syncwarp();
        // m[(a*4+d), r] = sum_b sv[a,b] M[b, r, d]
        {
            float4 acc0 = make_float4(0.f, 0.f, 0.f, 0.f);
            float4 acc1 = make_float4(0.f, 0.f, 0.f, 0.f);
            int a0 = 2 * hw, a1 = 2 * hw + 1;
            #pragma unroll
            for (int b = 0; b < 16; b++) {
                float4 Mb = *(const float4*)(s->M + b * 68 + rfix * 4);
                float s0 = sv[a0 * 16 + b], s1 = sv[a1 * 16 + b];
                acc0.x += s0 * Mb.x; acc0.y += s0 * Mb.y; acc0.z += s0 * Mb.z; acc0.w += s0 * Mb.w;
                acc1.x += s1 * Mb.x; acc1.y += s1 * Mb.y; acc1.z += s1 * Mb.z; acc1.w += s1 * Mb.w;
            }
            m[(a0 * 4 + 0) * 20 + rfix] = acc0.x;
            m[(a0 * 4 + 1) * 20 + rfix] = acc0.y;
            m[(a0 * 4 + 2) * 20 + rfix] = acc0.z;
            m[(a0 * 4 + 3) * 20 + rfix] = acc0.w;
            m[(a1 * 4 + 0) * 20 + rfix] = acc1.x;
            m[(a1 * 4 + 1) * 20 + rfix] = acc1.y;
            m[(a1 * 4 + 2) * 20 + rfix] = acc1.z;
            m[(a1 * 4 + 3) * 20 + rfix] = acc1.w;
        }
        __syncwarp();
        // W = m * F[bond j]
        {
            const float* Fj = s->F + (j - 1) * 256;
            float Fc[16];
            #pragma unroll
            for (int r2 = 0; r2 < 16; r2++) Fc[r2] = Fj[r2 * 16 + rfix];
            #pragma unroll
            for (int t = 0; t < 8; t++) {
                int rowp = hw + 2 * t;
                const float4* mr = (const float4*)(m + rowp * 20);
                float4 m0 = mr[0], m1 = mr[1], m2 = mr[2], m3 = mr[3];
                float acc = m0.x * Fc[0] + m0.y * Fc[1] + m0.z * Fc[2] + m0.w * Fc[3]
                          + m1.x * Fc[4] + m1.y * Fc[5] + m1.z * Fc[6] + m1.w * Fc[7]
                          + m2.x * Fc[8] + m2.y * Fc[9] + m2.z * Fc[10] + m2.w * Fc[11]
                          + m3.x * Fc[12] + m3.y * Fc[13] + m3.z * Fc[14] + m3.w * Fc[15];
                W[rowp * 16 + rfix] = acc;
            }
        }
        __syncwarp();
        // G = W * m^T (col-major)
        {
            const float4* mr = (const float4*)(m + rfix * 20);
            float4 c0 = mr[0], c1 = mr[1], c2 = mr[2], c3 = mr[3];
            #pragma unroll
            for (int t = 0; t < 8; t++) {
                int rowp = hw + 2 * t;
                const float4* Wp = (const float4*)(W + rowp * 16);
                float acc = d4(Wp[0], c0) + d4(Wp[1], c1) + d4(Wp[2], c2) + d4(Wp[3], c3);
                G[rfix * 20 + rowp] = acc;
            }
        }
        __syncwarp();
        jacobiSys(G, lane);
        __syncwarp();
        // column norms^2 = lambda^2
        if (lane < 16) {
            float n2 = 0.f;
            #pragma unroll
            for (int q = 0; q < 4; q++) {
                float4 g = *(float4*)(G + lane * 20 + q * 4);
                n2 += g.x * g.x + g.y * g.y + g.z * g.z + g.w * g.w;
            }
            s->cn[lane] = n2;
        }
        __syncwarp();
        if (lane == 0) {
            float dv[16];
            #pragma unroll
            for (int q = 0; q < 16; q++) dv[q] = s->cn[q];
            #pragma unroll
            for (int b = 0; b < 4; b++) {
                int bi = 0; float bv = dv[0];
                #pragma unroll
                for (int q = 1; q < 16; q++) if (dv[q] > bv) { bv = dv[q]; bi = q; }
                s->kidx[b] = bi; dv[bi] = -1.f;
                s->invn[b] = (bv > 1e-30f) ? rsqrtf(bv) : 0.f;
            }
        }
        __syncwarp();
        // small[j][(a*4+b)*4+d] = u_b[(a*4+d)] = G[:,kidx[b]] * invn[b]
        #pragma unroll
        for (int t = 0; t < 2; t++) {
            int e = lane + 32 * t;
            int d = e & 3, b = (e >> 2) & 3, a = e >> 4;
            s->small[j * 64 + e] = G[s->kidx[b] * 20 + (a * 4 + d)] * s->invn[b];
        }
        // sv[b, r] = invn[b] * sum_row G[row, kidx[b]] m[row, r] = u_b^T m
        #pragma unroll
        for (int t = 0; t < 2; t++) {
            int e = lane + 32 * t; int r = e & 15, b = e >> 4;
            int ci = s->kidx[b];
            float acc = 0.f;
            #pragma unroll
            for (int row = 0; row < 16; row++) acc += G[ci * 20 + row] * m[row * 20 + r];
            sv[e] = acc * s->invn[b];
        }
        __syncwarp();
    }
    // site 9
    commit8(s, v, lane); __syncwarp();
    absorb9<TOP>(s, lane); __syncwarp();
    if (lane < 16) {
        int d = lane & 3, a = lane >> 2;
        float acc = 0.f;
        #pragma unroll
        for (int b = 0; b < 16; b++) acc += sv[a * 16 + b] * s->M[b * 4 + d];
        s->small[9 * 64 + lane] = acc;
    }
    __syncwarp();
    // ---- Phase C: normalize + logn (guarded) ----
    float lacc = 0.f;
    for (int js = 0; js < 10; js++) {
        int n = (js == 0 || js == 9) ? 16 : 64;
        float ss = 0.f;
        for (int e = lane; e < n; e += 32) { float w = s->small[js * 64 + e]; ss += w * w; }
        ss = wsum(ss);
        float nrm = sqrtf(ss);
        float inv = (nrm > 1e-38f) ? (1.f / nrm) : 0.f;
        for (int e = lane; e < n; e += 32) s->small[js * 64 + e] *= inv;
        lacc += logf(fmaxf(nrm, 1e-38f));
    }
    if (lane == 0) s->logn += lacc;
    __syncwarp();
}

extern __shared__ float smraw[];

__global__ void __launch_bounds__(32)
amp_kernel(const int* __restrict__ x, const float* __restrict__ peps, float* __restrict__ out) {
    SM* s = (SM*)smraw;
    int lane = threadIdx.x;
    int blk = blockIdx.x;
    for (int e = lane; e < 100; e += 32) s->xr[e] = x[blk * 100 + e];
    if (lane == 0) s->logn = 0.f;
    __syncwarp();

    initRow<false>(s, peps, 0, lane);
    for (int i = 1; i <= 4; i++) compress<false>(s, peps, i, lane, 0);
    // bottom compressed MPS -> registers
    float br[20];
    #pragma unroll
    for (int t = 0; t < 20; t++) br[t] = s->small[lane + 32 * t];
    __syncwarp();

    initRow<true>(s, peps, 9, lane);
    for (int i = 8; i >= 5; i--) compress<true>(s, peps, i, lane, 0);

    // dump bottom MPS into the (dead) arena for the zip
    float* botS = s->A;
    #pragma unroll
    for (int t = 0; t < 20; t++) botS[lane + 32 * t] = br[t];
    __syncwarp();

    // ---- zip ----
    if (lane < 16) {
        int c = lane >> 2, e2 = lane & 3;
        float acc = 0.f;
        #pragma unroll
        for (int d = 0; d < 4; d++) acc += botS[c * 4 + d] * s->small[e2 * 4 + d];
        s->Eb[lane] = acc;
    }
    __syncwarp();
    for (int j = 1; j <= 8; j++) {
        if (lane < 16) {
            int c = lane >> 2, e2 = lane & 3;
            float acc = 0.f;
            #pragma unroll
            for (int a = 0; a < 4; a++)
                #pragma unroll
                for (int b = 0; b < 4; b++) {
                    float ev = s->Eb[a * 4 + b];
                    float dot = 0.f;
                    #pragma unroll
                    for (int d = 0; d < 4; d++)
                        dot += botS[j * 64 + (a * 4 + c) * 4 + d]
                             * s->small[j * 64 + (b * 4 + e2) * 4 + d];
                    acc += ev * dot;
                }
            s->Eb2[lane] = acc;
        }
        __syncwarp();
        if (lane < 16) s->Eb[lane] = s->Eb2[lane];
        __syncwarp();
    }
    float part = 0.f;
    if (lane < 16) {
        int a = lane >> 2, b = lane & 3;
        float dot = 0.f;
        #pragma unroll
        for (int d = 0; d < 4; d++)
            dot += botS[9 * 64 + a * 4 + d] * s->small[9 * 64 + b * 4 + d];
        part = s->Eb[a * 4 + b] * dot;
    }
    part = wsum(part);
    if (lane == 0) out[blk] = part * expf(s->logn);
}

extern "C" void kernel_launch(void* const* d_in, const int* in_sizes, int n_in,
                              void* d_out, int out_size) {
    const int* x;
    const float* peps;
    if (in_sizes[0] == 51200 && n_in >= 2) {
        peps = (const float*)d_in[0];
        x = (const int*)d_in[1];
    } else {
        x = (const int*)d_in[0];
        peps = (const float*)d_in[1];
    }
    float* out = (float*)d_out;
    cudaFuncSetAttribute(amp_kernel, cudaFuncAttributeMaxDynamicSharedMemorySize, (int)sizeof(SM));
    amp_kernel<<<out_size, 32, sizeof(SM)>>>(x, peps, out);
}